// round 1
// baseline (speedup 1.0000x reference)
#include <cuda_runtime.h>

#define N_NODES 50000
#define N_EDGES 800000
#define IN_DIM 300
#define HID 128
#define NLAYERS 4

// ---- scratch (device globals: allocation-free) ----
__device__ float g_reps[(NLAYERS + 1) * N_NODES * HID];  // h0..h4, 128 MB
__device__ float g_agg[N_NODES * HID];                   // mean-agg scratch / fusion tmp
__device__ float g_inv[N_NODES];                         // 1/max(deg,1)

// ---------------- degree ----------------
__global__ void deg_kernel(const int* __restrict__ ei) {
    int t = blockIdx.x * blockDim.x + threadIdx.x;
    if (t < N_EDGES) atomicAdd(&g_inv[ei[N_EDGES + t]], 1.0f);
}

__global__ void inv_kernel() {
    int t = blockIdx.x * blockDim.x + threadIdx.x;
    if (t < N_NODES) g_inv[t] = 1.0f / fmaxf(g_inv[t], 1.0f);
}

// ---------------- scatter-add aggregation (warp per edge) ----------------
__global__ void scatter_kernel(const int* __restrict__ ei, const float* __restrict__ h) {
    int gt = blockIdx.x * blockDim.x + threadIdx.x;
    int w = gt >> 5;
    if (w >= N_EDGES) return;
    int lane = gt & 31;
    int src = ei[w];
    int dst = ei[N_EDGES + w];
    float4 v = *(const float4*)(h + (size_t)src * HID + lane * 4);
    float* o = g_agg + (size_t)dst * HID + lane * 4;
    atomicAdd(o + 0, v.x);
    atomicAdd(o + 1, v.y);
    atomicAdd(o + 2, v.z);
    atomicAdd(o + 3, v.w);
}

// ---------------- fused GEMM family ----------------
// MODE 0: out = relu(A[N,300] @ W1[300,128] + bias)                       (embed)
// MODE 1: out = relu( LN( agg*inv @ W1 + bias + A2 @ W2 ) [+ skip] )     (SAGE layer)
// MODE 2: out = relu(reps_concat[N,640] @ W1[640,128] + bias)            (fusion 1)
// MODE 3: out = A[N,128] @ W1[128,128] + bias                            (fusion 2)
template <int MODE>
__global__ __launch_bounds__(256) void gemm_k(
    const float* __restrict__ A, const float* __restrict__ A2,
    const float* __restrict__ W1, const float* __restrict__ W2,
    const float* __restrict__ bias,
    const float* __restrict__ lng, const float* __restrict__ lnb,
    const float* __restrict__ skip,
    float* __restrict__ out)
{
    const int BK = 32, BM = 128, AST = 132;
    __shared__ __align__(16) float As[BK * AST];   // transposed: As[k][row]
    __shared__ __align__(16) float Ws[BK * HID];   // Ws[k][col]

    int tid = threadIdx.x;
    int tx = tid & 15;        // col group: cols tx*8 .. tx*8+7
    int ty = tid >> 4;        // row group: rows ty*8 .. ty*8+7
    int row0 = blockIdx.x * BM;

    float acc[8][8];
#pragma unroll
    for (int i = 0; i < 8; i++)
#pragma unroll
        for (int j = 0; j < 8; j++) acc[i][j] = 0.0f;

    const int nch = (MODE == 0) ? 10 : (MODE == 1) ? 8 : (MODE == 2) ? 20 : 4;

    for (int ch = 0; ch < nch; ++ch) {
        __syncthreads();
        // ---- load A tile (128 rows x 32 k), store transposed ----
#pragma unroll
        for (int p = 0; p < 4; p++) {
            int idx = tid + p * 256;      // 1024 float4
            int q = idx & 7;              // float4 index along k (8 per row)
            int r = idx >> 3;             // row in tile
            int grow = row0 + r;
            float4 v = make_float4(0.f, 0.f, 0.f, 0.f);
            if (grow < N_NODES) {
                if (MODE == 0) {
                    int kq = ch * BK + q * 4;
                    if (kq < IN_DIM) v = *(const float4*)(A + (size_t)grow * IN_DIM + kq);
                } else if (MODE == 1) {
                    if (ch < 4) {
                        v = *(const float4*)(A + (size_t)grow * HID + ch * BK + q * 4);
                        float s = g_inv[grow];
                        v.x *= s; v.y *= s; v.z *= s; v.w *= s;
                    } else {
                        v = *(const float4*)(A2 + (size_t)grow * HID + (ch - 4) * BK + q * 4);
                    }
                } else if (MODE == 2) {
                    int kg = ch * BK + q * 4;
                    int rep = kg >> 7;
                    int kl = kg & 127;
                    v = *(const float4*)(A + (size_t)rep * (N_NODES * HID) + (size_t)grow * HID + kl);
                } else {
                    v = *(const float4*)(A + (size_t)grow * HID + ch * BK + q * 4);
                }
            }
            As[(q * 4 + 0) * AST + r] = v.x;
            As[(q * 4 + 1) * AST + r] = v.y;
            As[(q * 4 + 2) * AST + r] = v.z;
            As[(q * 4 + 3) * AST + r] = v.w;
        }
        // ---- load W tile (32 k x 128 cols) ----
        const float* Wsrc = (MODE == 1 && ch >= 4) ? W2 : W1;
#pragma unroll
        for (int p = 0; p < 4; p++) {
            int idx = tid + p * 256;
            int c4 = idx & 31;
            int kk = idx >> 5;
            int wrow = (MODE == 1) ? ((ch & 3) * BK + kk) : (ch * BK + kk);
            float4 v = make_float4(0.f, 0.f, 0.f, 0.f);
            if (MODE != 0 || wrow < IN_DIM)
                v = *(const float4*)(Wsrc + (size_t)wrow * HID + c4 * 4);
            *(float4*)(Ws + kk * HID + c4 * 4) = v;
        }
        __syncthreads();
        // ---- compute ----
#pragma unroll
        for (int kk = 0; kk < BK; ++kk) {
            float a[8], b[8];
            *(float4*)(a)     = *(const float4*)(As + kk * AST + ty * 8);
            *(float4*)(a + 4) = *(const float4*)(As + kk * AST + ty * 8 + 4);
            *(float4*)(b)     = *(const float4*)(Ws + kk * HID + tx * 8);
            *(float4*)(b + 4) = *(const float4*)(Ws + kk * HID + tx * 8 + 4);
#pragma unroll
            for (int i = 0; i < 8; i++)
#pragma unroll
                for (int j = 0; j < 8; j++) acc[i][j] += a[i] * b[j];
        }
    }

    // ---- epilogue ----
    int c0 = tx * 8;
    float bv[8];
#pragma unroll
    for (int j = 0; j < 8; j++) bv[j] = bias[c0 + j];
#pragma unroll
    for (int i = 0; i < 8; i++)
#pragma unroll
        for (int j = 0; j < 8; j++) acc[i][j] += bv[j];

    if (MODE == 1) {
        float gv[8], be[8];
#pragma unroll
        for (int j = 0; j < 8; j++) { gv[j] = lng[c0 + j]; be[j] = lnb[c0 + j]; }
#pragma unroll
        for (int i = 0; i < 8; i++) {
            float s = 0.f, s2 = 0.f;
#pragma unroll
            for (int j = 0; j < 8; j++) { s += acc[i][j]; s2 += acc[i][j] * acc[i][j]; }
            // reduce across 16 lanes sharing this row (same ty within warp)
#pragma unroll
            for (int m = 1; m < 16; m <<= 1) {
                s  += __shfl_xor_sync(0xffffffffu, s,  m);
                s2 += __shfl_xor_sync(0xffffffffu, s2, m);
            }
            float mean = s * (1.0f / HID);
            float var = s2 * (1.0f / HID) - mean * mean;
            float rs = rsqrtf(var + 1e-5f);
            int grow = row0 + ty * 8 + i;
            if (grow < N_NODES) {
                float sk[8];
                if (skip) {
                    *(float4*)(sk)     = *(const float4*)(skip + (size_t)grow * HID + c0);
                    *(float4*)(sk + 4) = *(const float4*)(skip + (size_t)grow * HID + c0 + 4);
                }
                float o[8];
#pragma unroll
                for (int j = 0; j < 8; j++) {
                    float y = (acc[i][j] - mean) * rs * gv[j] + be[j];
                    if (skip) y += sk[j];
                    o[j] = fmaxf(y, 0.0f);
                }
                *(float4*)(out + (size_t)grow * HID + c0)     = *(float4*)(o);
                *(float4*)(out + (size_t)grow * HID + c0 + 4) = *(float4*)(o + 4);
            }
        }
    } else {
#pragma unroll
        for (int i = 0; i < 8; i++) {
            int grow = row0 + ty * 8 + i;
            if (grow < N_NODES) {
                float o[8];
#pragma unroll
                for (int j = 0; j < 8; j++)
                    o[j] = (MODE == 3) ? acc[i][j] : fmaxf(acc[i][j], 0.0f);
                *(float4*)(out + (size_t)grow * HID + c0)     = *(float4*)(o);
                *(float4*)(out + (size_t)grow * HID + c0 + 4) = *(float4*)(o + 4);
            }
        }
    }
}

// ---------------- launch ----------------
extern "C" void kernel_launch(void* const* d_in, const int* in_sizes, int n_in,
                              void* d_out, int out_size)
{
    const float* x       = (const float*)d_in[0];
    const int*   ei      = (const int*)  d_in[1];
    const float* emb_W   = (const float*)d_in[2];
    const float* emb_b   = (const float*)d_in[3];
    const float* lin_l_W = (const float*)d_in[4];
    const float* lin_l_b = (const float*)d_in[5];
    const float* lin_r_W = (const float*)d_in[6];
    const float* ln_g    = (const float*)d_in[7];
    const float* ln_b    = (const float*)d_in[8];
    const float* fus_W1  = (const float*)d_in[9];
    const float* fus_b1  = (const float*)d_in[10];
    const float* fus_W2  = (const float*)d_in[11];
    const float* fus_b2  = (const float*)d_in[12];
    float* out = (float*)d_out;

    float *reps, *agg, *inv;
    cudaGetSymbolAddress((void**)&reps, g_reps);
    cudaGetSymbolAddress((void**)&agg,  g_agg);
    cudaGetSymbolAddress((void**)&inv,  g_inv);

    // degree / inv_deg
    cudaMemsetAsync(inv, 0, N_NODES * sizeof(float));
    deg_kernel<<<(N_EDGES + 255) / 256, 256>>>(ei);
    inv_kernel<<<(N_NODES + 255) / 256, 256>>>();

    const int GB = (N_NODES + 127) / 128;

    // embedding: h0 = relu(x @ emb_W + emb_b)
    gemm_k<0><<<GB, 256>>>(x, nullptr, emb_W, nullptr, emb_b,
                           nullptr, nullptr, nullptr, reps);

    for (int i = 0; i < NLAYERS; i++) {
        float* h  = reps + (size_t)i * N_NODES * HID;
        float* hn = reps + (size_t)(i + 1) * N_NODES * HID;
        cudaMemsetAsync(agg, 0, (size_t)N_NODES * HID * sizeof(float));
        scatter_kernel<<<(N_EDGES * 32 + 255) / 256, 256>>>(ei, h);
        gemm_k<1><<<GB, 256>>>(agg, h,
                               lin_l_W + (size_t)i * HID * HID,
                               lin_r_W + (size_t)i * HID * HID,
                               lin_l_b + i * HID,
                               ln_g + i * HID, ln_b + i * HID,
                               (i > 0) ? h : nullptr, hn);
    }

    // fusion
    gemm_k<2><<<GB, 256>>>(reps, nullptr, fus_W1, nullptr, fus_b1,
                           nullptr, nullptr, nullptr, agg);
    gemm_k<3><<<GB, 256>>>(agg, nullptr, fus_W2, nullptr, fus_b2,
                           nullptr, nullptr, nullptr, out);
}

// round 2
// speedup vs baseline: 1.6093x; 1.6093x over previous
#include <cuda_runtime.h>

#define N_NODES 50000
#define N_EDGES 800000
#define IN_DIM 300
#define HID 128
#define NLAYERS 4

// ---- scratch (device globals: allocation-free) ----
__device__ float g_reps[(NLAYERS + 1) * N_NODES * HID];  // h0..h4
__device__ float g_agg[N_NODES * HID];                   // mean-agg scratch / fusion tmp
__device__ float g_inv[N_NODES];                         // 1/max(deg,1)
__device__ int   g_degi[N_NODES];
__device__ int   g_rowptr[N_NODES + 1];
__device__ int   g_cursor[N_NODES];
__device__ int   g_col[N_EDGES];

// ---------------- degree histogram (int) ----------------
__global__ void deg_kernel(const int* __restrict__ ei) {
    int t = blockIdx.x * blockDim.x + threadIdx.x;
    if (t < N_EDGES) atomicAdd(&g_degi[ei[N_EDGES + t]], 1);
}

__global__ void inv_kernel() {
    int t = blockIdx.x * blockDim.x + threadIdx.x;
    if (t < N_NODES) g_inv[t] = 1.0f / (float)max(g_degi[t], 1);
}

// ---------------- exclusive scan over degrees (1 block) ----------------
__global__ __launch_bounds__(1024) void scan_kernel() {
    __shared__ int partial[1024];
    const int CH = (N_NODES + 1023) / 1024;  // 49
    int tid = threadIdx.x;
    int base = tid * CH;
    int s = 0;
    for (int i = 0; i < CH; i++) {
        int idx = base + i;
        if (idx < N_NODES) s += g_degi[idx];
    }
    partial[tid] = s;
    __syncthreads();
    // Hillis-Steele inclusive scan over 1024 partials
    for (int off = 1; off < 1024; off <<= 1) {
        int v = (tid >= off) ? partial[tid - off] : 0;
        __syncthreads();
        partial[tid] += v;
        __syncthreads();
    }
    int run = partial[tid] - s;  // exclusive prefix of this chunk
    for (int i = 0; i < CH; i++) {
        int idx = base + i;
        if (idx < N_NODES) {
            g_rowptr[idx] = run;
            g_cursor[idx] = run;
            run += g_degi[idx];
        }
    }
    if (tid == 1023) g_rowptr[N_NODES] = N_EDGES;
}

// ---------------- CSR fill: sort edges by dst ----------------
__global__ void fill_kernel(const int* __restrict__ ei) {
    int t = blockIdx.x * blockDim.x + threadIdx.x;
    if (t >= N_EDGES) return;
    int dst = ei[N_EDGES + t];
    int pos = atomicAdd(&g_cursor[dst], 1);
    g_col[pos] = ei[t];
}

// ---------------- gather-only mean aggregation (warp per node) ----------------
__global__ __launch_bounds__(256) void agg_kernel(const float* __restrict__ h) {
    int gt = blockIdx.x * blockDim.x + threadIdx.x;
    int node = gt >> 5;
    if (node >= N_NODES) return;
    int lane = gt & 31;
    int beg = g_rowptr[node];
    int end = g_rowptr[node + 1];

    float ax = 0.f, ay = 0.f, az = 0.f, aw = 0.f;
    int e = beg;
    for (; e + 4 <= end; e += 4) {
        int s0 = __ldg(&g_col[e + 0]);
        int s1 = __ldg(&g_col[e + 1]);
        int s2 = __ldg(&g_col[e + 2]);
        int s3 = __ldg(&g_col[e + 3]);
        float4 v0 = *(const float4*)(h + (size_t)s0 * HID + lane * 4);
        float4 v1 = *(const float4*)(h + (size_t)s1 * HID + lane * 4);
        float4 v2 = *(const float4*)(h + (size_t)s2 * HID + lane * 4);
        float4 v3 = *(const float4*)(h + (size_t)s3 * HID + lane * 4);
        ax += v0.x + v1.x + v2.x + v3.x;
        ay += v0.y + v1.y + v2.y + v3.y;
        az += v0.z + v1.z + v2.z + v3.z;
        aw += v0.w + v1.w + v2.w + v3.w;
    }
    for (; e < end; e++) {
        int s = __ldg(&g_col[e]);
        float4 v = *(const float4*)(h + (size_t)s * HID + lane * 4);
        ax += v.x; ay += v.y; az += v.z; aw += v.w;
    }
    float inv = g_inv[node];
    float4 o = make_float4(ax * inv, ay * inv, az * inv, aw * inv);
    *(float4*)(g_agg + (size_t)node * HID + lane * 4) = o;
}

// ---------------- fused GEMM family ----------------
// MODE 0: out = relu(A[N,300] @ W1[300,128] + bias)                       (embed)
// MODE 1: out = relu( LN( agg @ W1 + bias + A2 @ W2 ) [+ skip] )          (SAGE layer)
// MODE 2: out = relu(reps_concat[N,640] @ W1[640,128] + bias)             (fusion 1)
// MODE 3: out = A[N,128] @ W1[128,128] + bias                             (fusion 2)
template <int MODE>
__global__ __launch_bounds__(256) void gemm_k(
    const float* __restrict__ A, const float* __restrict__ A2,
    const float* __restrict__ W1, const float* __restrict__ W2,
    const float* __restrict__ bias,
    const float* __restrict__ lng, const float* __restrict__ lnb,
    const float* __restrict__ skip,
    float* __restrict__ out)
{
    const int BK = 32, BM = 128, AST = 132;
    __shared__ __align__(16) float As[BK * AST];   // transposed: As[k][row]
    __shared__ __align__(16) float Ws[BK * HID];   // Ws[k][col]

    int tid = threadIdx.x;
    int tx = tid & 15;        // col group: cols tx*8 .. tx*8+7
    int ty = tid >> 4;        // row group: rows ty*8 .. ty*8+7
    int row0 = blockIdx.x * BM;

    float acc[8][8];
#pragma unroll
    for (int i = 0; i < 8; i++)
#pragma unroll
        for (int j = 0; j < 8; j++) acc[i][j] = 0.0f;

    const int nch = (MODE == 0) ? 10 : (MODE == 1) ? 8 : (MODE == 2) ? 20 : 4;

    for (int ch = 0; ch < nch; ++ch) {
        __syncthreads();
        // ---- load A tile (128 rows x 32 k), store transposed ----
#pragma unroll
        for (int p = 0; p < 4; p++) {
            int idx = tid + p * 256;      // 1024 float4
            int q = idx & 7;              // float4 index along k (8 per row)
            int r = idx >> 3;             // row in tile
            int grow = row0 + r;
            float4 v = make_float4(0.f, 0.f, 0.f, 0.f);
            if (grow < N_NODES) {
                if (MODE == 0) {
                    int kq = ch * BK + q * 4;
                    if (kq < IN_DIM) v = *(const float4*)(A + (size_t)grow * IN_DIM + kq);
                } else if (MODE == 1) {
                    if (ch < 4)
                        v = *(const float4*)(A + (size_t)grow * HID + ch * BK + q * 4);
                    else
                        v = *(const float4*)(A2 + (size_t)grow * HID + (ch - 4) * BK + q * 4);
                } else if (MODE == 2) {
                    int kg = ch * BK + q * 4;
                    int rep = kg >> 7;
                    int kl = kg & 127;
                    v = *(const float4*)(A + (size_t)rep * (N_NODES * HID) + (size_t)grow * HID + kl);
                } else {
                    v = *(const float4*)(A + (size_t)grow * HID + ch * BK + q * 4);
                }
            }
            As[(q * 4 + 0) * AST + r] = v.x;
            As[(q * 4 + 1) * AST + r] = v.y;
            As[(q * 4 + 2) * AST + r] = v.z;
            As[(q * 4 + 3) * AST + r] = v.w;
        }
        // ---- load W tile (32 k x 128 cols) ----
        const float* Wsrc = (MODE == 1 && ch >= 4) ? W2 : W1;
#pragma unroll
        for (int p = 0; p < 4; p++) {
            int idx = tid + p * 256;
            int c4 = idx & 31;
            int kk = idx >> 5;
            int wrow = (MODE == 1) ? ((ch & 3) * BK + kk) : (ch * BK + kk);
            float4 v = make_float4(0.f, 0.f, 0.f, 0.f);
            if (MODE != 0 || wrow < IN_DIM)
                v = *(const float4*)(Wsrc + (size_t)wrow * HID + c4 * 4);
            *(float4*)(Ws + kk * HID + c4 * 4) = v;
        }
        __syncthreads();
        // ---- compute ----
#pragma unroll
        for (int kk = 0; kk < BK; ++kk) {
            float a[8], b[8];
            *(float4*)(a)     = *(const float4*)(As + kk * AST + ty * 8);
            *(float4*)(a + 4) = *(const float4*)(As + kk * AST + ty * 8 + 4);
            *(float4*)(b)     = *(const float4*)(Ws + kk * HID + tx * 8);
            *(float4*)(b + 4) = *(const float4*)(Ws + kk * HID + tx * 8 + 4);
#pragma unroll
            for (int i = 0; i < 8; i++)
#pragma unroll
                for (int j = 0; j < 8; j++) acc[i][j] += a[i] * b[j];
        }
    }

    // ---- epilogue ----
    int c0 = tx * 8;
    float bv[8];
#pragma unroll
    for (int j = 0; j < 8; j++) bv[j] = bias[c0 + j];
#pragma unroll
    for (int i = 0; i < 8; i++)
#pragma unroll
        for (int j = 0; j < 8; j++) acc[i][j] += bv[j];

    if (MODE == 1) {
        float gv[8], be[8];
#pragma unroll
        for (int j = 0; j < 8; j++) { gv[j] = lng[c0 + j]; be[j] = lnb[c0 + j]; }
#pragma unroll
        for (int i = 0; i < 8; i++) {
            float s = 0.f, s2 = 0.f;
#pragma unroll
            for (int j = 0; j < 8; j++) { s += acc[i][j]; s2 += acc[i][j] * acc[i][j]; }
#pragma unroll
            for (int m = 1; m < 16; m <<= 1) {
                s  += __shfl_xor_sync(0xffffffffu, s,  m);
                s2 += __shfl_xor_sync(0xffffffffu, s2, m);
            }
            float mean = s * (1.0f / HID);
            float var = s2 * (1.0f / HID) - mean * mean;
            float rs = rsqrtf(var + 1e-5f);
            int grow = row0 + ty * 8 + i;
            if (grow < N_NODES) {
                float sk[8];
                if (skip) {
                    *(float4*)(sk)     = *(const float4*)(skip + (size_t)grow * HID + c0);
                    *(float4*)(sk + 4) = *(const float4*)(skip + (size_t)grow * HID + c0 + 4);
                }
                float o[8];
#pragma unroll
                for (int j = 0; j < 8; j++) {
                    float y = (acc[i][j] - mean) * rs * gv[j] + be[j];
                    if (skip) y += sk[j];
                    o[j] = fmaxf(y, 0.0f);
                }
                *(float4*)(out + (size_t)grow * HID + c0)     = *(float4*)(o);
                *(float4*)(out + (size_t)grow * HID + c0 + 4) = *(float4*)(o + 4);
            }
        }
    } else {
#pragma unroll
        for (int i = 0; i < 8; i++) {
            int grow = row0 + ty * 8 + i;
            if (grow < N_NODES) {
                float o[8];
#pragma unroll
                for (int j = 0; j < 8; j++)
                    o[j] = (MODE == 3) ? acc[i][j] : fmaxf(acc[i][j], 0.0f);
                *(float4*)(out + (size_t)grow * HID + c0)     = *(float4*)(o);
                *(float4*)(out + (size_t)grow * HID + c0 + 4) = *(float4*)(o + 4);
            }
        }
    }
}

// ---------------- launch ----------------
extern "C" void kernel_launch(void* const* d_in, const int* in_sizes, int n_in,
                              void* d_out, int out_size)
{
    const float* x       = (const float*)d_in[0];
    const int*   ei      = (const int*)  d_in[1];
    const float* emb_W   = (const float*)d_in[2];
    const float* emb_b   = (const float*)d_in[3];
    const float* lin_l_W = (const float*)d_in[4];
    const float* lin_l_b = (const float*)d_in[5];
    const float* lin_r_W = (const float*)d_in[6];
    const float* ln_g    = (const float*)d_in[7];
    const float* ln_b    = (const float*)d_in[8];
    const float* fus_W1  = (const float*)d_in[9];
    const float* fus_b1  = (const float*)d_in[10];
    const float* fus_W2  = (const float*)d_in[11];
    const float* fus_b2  = (const float*)d_in[12];
    float* out = (float*)d_out;

    float *reps, *agg;
    int *degi;
    cudaGetSymbolAddress((void**)&reps, g_reps);
    cudaGetSymbolAddress((void**)&agg,  g_agg);
    cudaGetSymbolAddress((void**)&degi, g_degi);

    // build CSR (dst-sorted) + inv_deg
    cudaMemsetAsync(degi, 0, N_NODES * sizeof(int));
    deg_kernel<<<(N_EDGES + 255) / 256, 256>>>(ei);
    inv_kernel<<<(N_NODES + 255) / 256, 256>>>();
    scan_kernel<<<1, 1024>>>();
    fill_kernel<<<(N_EDGES + 255) / 256, 256>>>(ei);

    const int GB = (N_NODES + 127) / 128;

    // embedding: h0 = relu(x @ emb_W + emb_b)
    gemm_k<0><<<GB, 256>>>(x, nullptr, emb_W, nullptr, emb_b,
                           nullptr, nullptr, nullptr, reps);

    for (int i = 0; i < NLAYERS; i++) {
        float* h  = reps + (size_t)i * N_NODES * HID;
        float* hn = reps + (size_t)(i + 1) * N_NODES * HID;
        agg_kernel<<<(N_NODES * 32 + 255) / 256, 256>>>(h);
        gemm_k<1><<<GB, 256>>>(agg, h,
                               lin_l_W + (size_t)i * HID * HID,
                               lin_r_W + (size_t)i * HID * HID,
                               lin_l_b + i * HID,
                               ln_g + i * HID, ln_b + i * HID,
                               (i > 0) ? h : nullptr, hn);
    }

    // fusion
    gemm_k<2><<<GB, 256>>>(reps, nullptr, fus_W1, nullptr, fus_b1,
                           nullptr, nullptr, nullptr, agg);
    gemm_k<3><<<GB, 256>>>(agg, nullptr, fus_W2, nullptr, fus_b2,
                           nullptr, nullptr, nullptr, out);
}

// round 5
// speedup vs baseline: 2.5987x; 1.6148x over previous
#include <cuda_runtime.h>
#include <cuda_bf16.h>
#include <cstdint>

#define N_NODES 50000
#define N_EDGES 800000
#define IN_DIM 300
#define HID 128
#define NLAYERS 4

// ---------------- device scratch (allocation-free) ----------------
__device__ float g_reps[(NLAYERS + 1) * N_NODES * HID];
__device__ float g_agg[N_NODES * HID];
__device__ float g_inv[N_NODES];
__device__ int   g_degi[N_NODES];
__device__ int   g_rowptr[N_NODES + 1];
__device__ int   g_cursor[N_NODES];
__device__ int   g_col[N_EDGES];
// pre-transposed weight chunks, bf16 hi/lo: 33 chunks x [128 n x 32 words(64 bf16 k)]
__device__ unsigned int g_whi[33 * 4096];
__device__ unsigned int g_wlo[33 * 4096];

// ---------------- helpers ----------------
__device__ __forceinline__ uint32_t smem_to_u32(const void* p) {
    uint32_t a;
    asm("{ .reg .u64 t; cvta.to.shared.u64 t, %1; cvt.u32.u64 %0, t; }" : "=r"(a) : "l"(p));
    return a;
}
__device__ __forceinline__ void ldsm4(uint32_t* r, uint32_t a) {
    asm volatile("ldmatrix.sync.aligned.m8n8.x4.shared.b16 {%0,%1,%2,%3}, [%4];"
                 : "=r"(r[0]), "=r"(r[1]), "=r"(r[2]), "=r"(r[3]) : "r"(a));
}
__device__ __forceinline__ void ldsm2(uint32_t* r, uint32_t a) {
    asm volatile("ldmatrix.sync.aligned.m8n8.x2.shared.b16 {%0,%1}, [%2];"
                 : "=r"(r[0]), "=r"(r[1]) : "r"(a));
}
__device__ __forceinline__ void mma16816(float* c, const uint32_t* a, const uint32_t* b) {
    asm volatile(
        "mma.sync.aligned.m16n8k16.row.col.f32.bf16.bf16.f32 "
        "{%0,%1,%2,%3},{%4,%5,%6,%7},{%8,%9},{%0,%1,%2,%3};"
        : "+f"(c[0]), "+f"(c[1]), "+f"(c[2]), "+f"(c[3])
        : "r"(a[0]), "r"(a[1]), "r"(a[2]), "r"(a[3]), "r"(b[0]), "r"(b[1]));
}
__device__ __forceinline__ unsigned pack_hi(float a, float b, float& ra, float& rb) {
    __nv_bfloat16 ha = __float2bfloat16(a), hb = __float2bfloat16(b);
    ra = a - __bfloat162float(ha);
    rb = b - __bfloat162float(hb);
    return (unsigned)__bfloat16_as_ushort(ha) | ((unsigned)__bfloat16_as_ushort(hb) << 16);
}
__device__ __forceinline__ unsigned pack_lo(float ra, float rb) {
    return (unsigned)__bfloat16_as_ushort(__float2bfloat16(ra)) |
           ((unsigned)__bfloat16_as_ushort(__float2bfloat16(rb)) << 16);
}

// ---------------- CSR build ----------------
__global__ void deg_kernel(const int* __restrict__ ei) {
    int t = blockIdx.x * blockDim.x + threadIdx.x;
    if (t < N_EDGES) atomicAdd(&g_degi[ei[N_EDGES + t]], 1);
}
__global__ void inv_kernel() {
    int t = blockIdx.x * blockDim.x + threadIdx.x;
    if (t < N_NODES) g_inv[t] = 1.0f / (float)max(g_degi[t], 1);
}
__global__ __launch_bounds__(1024) void scan_kernel() {
    __shared__ int partial[1024];
    const int CH = (N_NODES + 1023) / 1024;
    int tid = threadIdx.x;
    int base = tid * CH;
    int s = 0;
    for (int i = 0; i < CH; i++) { int idx = base + i; if (idx < N_NODES) s += g_degi[idx]; }
    partial[tid] = s;
    __syncthreads();
    for (int off = 1; off < 1024; off <<= 1) {
        int v = (tid >= off) ? partial[tid - off] : 0;
        __syncthreads();
        partial[tid] += v;
        __syncthreads();
    }
    int run = partial[tid] - s;
    for (int i = 0; i < CH; i++) {
        int idx = base + i;
        if (idx < N_NODES) { g_rowptr[idx] = run; g_cursor[idx] = run; run += g_degi[idx]; }
    }
    if (tid == 1023) g_rowptr[N_NODES] = N_EDGES;
}
__global__ void fill_kernel(const int* __restrict__ ei) {
    int t = blockIdx.x * blockDim.x + threadIdx.x;
    if (t >= N_EDGES) return;
    int dst = ei[N_EDGES + t];
    int pos = atomicAdd(&g_cursor[dst], 1);
    g_col[pos] = ei[t];
}

// ---------------- gather-only mean aggregation (warp per node) ----------------
__global__ __launch_bounds__(256) void agg_kernel(const float* __restrict__ h) {
    int gt = blockIdx.x * blockDim.x + threadIdx.x;
    int node = gt >> 5;
    if (node >= N_NODES) return;
    int lane = gt & 31;
    int beg = g_rowptr[node];
    int end = g_rowptr[node + 1];
    float ax = 0.f, ay = 0.f, az = 0.f, aw = 0.f;
    int e = beg;
    for (; e + 4 <= end; e += 4) {
        int s0 = __ldg(&g_col[e + 0]);
        int s1 = __ldg(&g_col[e + 1]);
        int s2 = __ldg(&g_col[e + 2]);
        int s3 = __ldg(&g_col[e + 3]);
        float4 v0 = *(const float4*)(h + (size_t)s0 * HID + lane * 4);
        float4 v1 = *(const float4*)(h + (size_t)s1 * HID + lane * 4);
        float4 v2 = *(const float4*)(h + (size_t)s2 * HID + lane * 4);
        float4 v3 = *(const float4*)(h + (size_t)s3 * HID + lane * 4);
        ax += v0.x + v1.x + v2.x + v3.x;
        ay += v0.y + v1.y + v2.y + v3.y;
        az += v0.z + v1.z + v2.z + v3.z;
        aw += v0.w + v1.w + v2.w + v3.w;
    }
    for (; e < end; e++) {
        int s = __ldg(&g_col[e]);
        float4 v = *(const float4*)(h + (size_t)s * HID + lane * 4);
        ax += v.x; ay += v.y; az += v.z; aw += v.w;
    }
    float inv = g_inv[node];
    float4 o = make_float4(ax * inv, ay * inv, az * inv, aw * inv);
    *(float4*)(g_agg + (size_t)node * HID + lane * 4) = o;
}

// ---------------- weight prep: transpose + bf16 hi/lo split ----------------
// chunk map: 0-4 embed (K=300 pad 320), 5..20 layers (L*4+c, K=256: lin_l|lin_r),
//            21-30 fus1 (K=640), 31-32 fus2 (K=128)
// layout per chunk: [n(128) x 32 words], word w holds bf16 pair (k=2w, 2w+1)
__global__ void prep_w(const float* __restrict__ embW, const float* __restrict__ llW,
                       const float* __restrict__ lrW, const float* __restrict__ f1W,
                       const float* __restrict__ f2W) {
    int t = blockIdx.x * blockDim.x + threadIdx.x;
    if (t >= 33 * 4096) return;
    int chunk = t >> 12, w = t & 4095, n = w >> 5, kp = w & 31, k = kp * 2;
    float v0 = 0.f, v1 = 0.f;
    if (chunk < 5) {
        int kg = chunk * 64 + k;
        if (kg < IN_DIM)     v0 = embW[(size_t)kg * HID + n];
        if (kg + 1 < IN_DIM) v1 = embW[(size_t)(kg + 1) * HID + n];
    } else if (chunk < 21) {
        int L = (chunk - 5) >> 2, c = (chunk - 5) & 3;
        int kg = c * 64 + k;
        const float* W = (kg < 128) ? (llW + (size_t)L * HID * HID + (size_t)kg * HID)
                                    : (lrW + (size_t)L * HID * HID + (size_t)(kg - 128) * HID);
        v0 = W[n]; v1 = W[HID + n];
    } else if (chunk < 31) {
        int kg = (chunk - 21) * 64 + k;
        v0 = f1W[(size_t)kg * HID + n]; v1 = f1W[(size_t)(kg + 1) * HID + n];
    } else {
        int kg = (chunk - 31) * 64 + k;
        v0 = f2W[(size_t)kg * HID + n]; v1 = f2W[(size_t)(kg + 1) * HID + n];
    }
    float r0, r1;
    unsigned hp = pack_hi(v0, v1, r0, r1);
    unsigned lp = pack_lo(r0, r1);
    g_whi[chunk * 4096 + n * 32 + kp] = hp;
    g_wlo[chunk * 4096 + n * 32 + kp] = lp;
}

// ---------------- mma.sync GEMM family ----------------
// smem: header [bias 512 | g 512 | b 512], tiles (stride 144B/row):
#define OFF_BIAS 0
#define OFF_G    512
#define OFF_B    1024
#define OFF_AH   2048
#define OFF_AL   (OFF_AH + 128 * 144)   // 20480
#define OFF_BH   (OFF_AL + 128 * 144)   // 38912
#define OFF_BL   (OFF_BH + 128 * 144)   // 57344
#define SMEM_TOTAL (OFF_BL + 128 * 144) // 75776
#define OFF_BOUNCE OFF_AH               // reused after mainloop
#define BSTRIDE 132

// MODE 0: relu(x @ embW + b)                       K=300 (5 chunks)
// MODE 1: relu(LN(agg@Wl + b + h@Wr) [+skip])      K=256 (4 chunks)
// MODE 2: relu(concat @ fusW1 + b)                 K=640 (10 chunks)
// MODE 3: A @ fusW2 + b                            K=128 (2 chunks)
template <int MODE>
__global__ __launch_bounds__(256)
void gemm_mma(const float* __restrict__ A, const float* __restrict__ A2, int wc0,
              const float* __restrict__ bias, const float* __restrict__ lng,
              const float* __restrict__ lnb, const float* __restrict__ skip,
              float* __restrict__ out)
{
    extern __shared__ char smem[];
    uint32_t sb = smem_to_u32(smem);
    int tid = threadIdx.x, wid = tid >> 5, lane = tid & 31;
    int warp_m = wid & 3, warp_n = wid >> 2;           // 4 x 2 warp grid
    int row0 = blockIdx.x * 128;
    const int nch = (MODE == 0) ? 5 : (MODE == 1) ? 4 : (MODE == 2) ? 10 : 2;

    if (tid < HID) {
        *(float*)(smem + OFF_BIAS + tid * 4) = bias[tid];
        if (MODE == 1) {
            *(float*)(smem + OFF_G + tid * 4) = lng[tid];
            *(float*)(smem + OFF_B + tid * 4) = lnb[tid];
        }
    }

    float acc[2][8][4];
#pragma unroll
    for (int mt = 0; mt < 2; mt++)
#pragma unroll
        for (int nt = 0; nt < 8; nt++)
#pragma unroll
            for (int q = 0; q < 4; q++) acc[mt][nt][q] = 0.f;

    // ldmatrix lane offsets
    uint32_t aOff = sb + (uint32_t)((warp_m * 32 + (lane & 15)) * 144 + (lane >> 4) * 16);
    uint32_t bOff = sb + (uint32_t)((warp_n * 64 + (lane & 7)) * 144 + ((lane >> 3) & 1) * 16);

    for (int c = 0; c < nch; ++c) {
        __syncthreads();
        // ---- fill A_hi / A_lo (128 rows x 64 k bf16, 144B stride) ----
#pragma unroll
        for (int it = 0; it < 8; ++it) {
            int idx = tid + it * 256;       // 2048 quads
            int row = idx >> 4, q = idx & 15, k = q * 4;
            int kg = c * 64 + k, grow = row0 + row;
            float4 v = make_float4(0.f, 0.f, 0.f, 0.f);
            if (grow < N_NODES) {
                if (MODE == 0) {
                    if (kg < IN_DIM) v = *(const float4*)(A + (size_t)grow * IN_DIM + kg);
                } else if (MODE == 1) {
                    v = (kg < 128) ? *(const float4*)(A  + (size_t)grow * HID + kg)
                                   : *(const float4*)(A2 + (size_t)grow * HID + kg - 128);
                } else if (MODE == 2) {
                    int rep = kg >> 7;
                    v = *(const float4*)(A + (size_t)rep * ((size_t)N_NODES * HID) +
                                         (size_t)grow * HID + (kg & 127));
                } else {
                    v = *(const float4*)(A + (size_t)grow * HID + kg);
                }
            }
            float r0, r1, r2, r3;
            unsigned h01 = pack_hi(v.x, v.y, r0, r1);
            unsigned h23 = pack_hi(v.z, v.w, r2, r3);
            unsigned l01 = pack_lo(r0, r1);
            unsigned l23 = pack_lo(r2, r3);
            int off = row * 144 + k * 2;
            *(uint2*)(smem + OFF_AH + off) = make_uint2(h01, h23);
            *(uint2*)(smem + OFF_AL + off) = make_uint2(l01, l23);
        }
        // ---- copy B chunk (128 n-rows x 32 words) ----
        {
            const uint4* srcH = (const uint4*)(g_whi + (size_t)(wc0 + c) * 4096);
            const uint4* srcL = (const uint4*)(g_wlo + (size_t)(wc0 + c) * 4096);
#pragma unroll
            for (int it = 0; it < 4; ++it) {
                int idx = tid + it * 256;   // 1024 uint4
                int row = idx >> 3, j = idx & 7;
                int off = row * 144 + j * 16;
                *(uint4*)(smem + OFF_BH + off) = srcH[idx];
                *(uint4*)(smem + OFF_BL + off) = srcL[idx];
            }
        }
        __syncthreads();
        // ---- compute: 4 k16 steps ----
#pragma unroll
        for (int ks = 0; ks < 4; ++ks) {
            uint32_t ah[2][4], al[2][4];
#pragma unroll
            for (int mt = 0; mt < 2; mt++) {
                ldsm4(ah[mt], aOff + OFF_AH - OFF_AH + (OFF_AH & 0) + (uint32_t)(OFF_AH) + mt * 16 * 144 + ks * 32 - sb + sb);
            }
            // (recompute cleanly below)
#pragma unroll
            for (int mt = 0; mt < 2; mt++) {
                ldsm4(ah[mt], aOff + OFF_AH + mt * 16 * 144 + ks * 32);
                ldsm4(al[mt], aOff + OFF_AL + mt * 16 * 144 + ks * 32);
            }
#pragma unroll
            for (int nt = 0; nt < 8; ++nt) {
                uint32_t bh[2], bl[2];
                ldsm2(bh, bOff + OFF_BH + nt * 8 * 144 + ks * 32);
                ldsm2(bl, bOff + OFF_BL + nt * 8 * 144 + ks * 32);
#pragma unroll
                for (int mt = 0; mt < 2; mt++) {
                    mma16816(acc[mt][nt], ah[mt], bh);
                    mma16816(acc[mt][nt], ah[mt], bl);
                    mma16816(acc[mt][nt], al[mt], bh);
                }
            }
        }
    }
    __syncthreads();

    // ---- dump accs (+bias, +relu for MODE 0/2) to bounce ----
    {
        float* bounce = (float*)(smem + OFF_BOUNCE);
        const float* sbias = (const float*)(smem + OFF_BIAS);
        int tq = lane >> 2, tr = lane & 3;
#pragma unroll
        for (int mt = 0; mt < 2; mt++) {
#pragma unroll
            for (int nt = 0; nt < 8; nt++) {
                int col = warp_n * 64 + nt * 8 + tr * 2;
                float b0 = sbias[col], b1 = sbias[col + 1];
                int r0 = warp_m * 32 + mt * 16 + tq;
                float x0 = acc[mt][nt][0] + b0, x1 = acc[mt][nt][1] + b1;
                float x2 = acc[mt][nt][2] + b0, x3 = acc[mt][nt][3] + b1;
                if (MODE == 0 || MODE == 2) {
                    x0 = fmaxf(x0, 0.f); x1 = fmaxf(x1, 0.f);
                    x2 = fmaxf(x2, 0.f); x3 = fmaxf(x3, 0.f);
                }
                *(float2*)(bounce + r0 * BSTRIDE + col)       = make_float2(x0, x1);
                *(float2*)(bounce + (r0 + 8) * BSTRIDE + col) = make_float2(x2, x3);
            }
        }
    }
    __syncthreads();

    // ---- LN pass (MODE 1): thread per row ----
    if (MODE == 1 && tid < 128) {
        float* bounce = (float*)(smem + OFF_BOUNCE);
        const float* sg = (const float*)(smem + OFF_G);
        const float* sbe = (const float*)(smem + OFF_B);
        float s = 0.f, s2 = 0.f;
#pragma unroll
        for (int j = 0; j < HID; j++) {
            float x = bounce[tid * BSTRIDE + j];
            s += x; s2 += x * x;
        }
        float mean = s * (1.0f / HID);
        float var = s2 * (1.0f / HID) - mean * mean;
        float rs = rsqrtf(var + 1e-5f);
#pragma unroll
        for (int j = 0; j < HID; j++) {
            float x = bounce[tid * BSTRIDE + j];
            bounce[tid * BSTRIDE + j] = (x - mean) * rs * sg[j] + sbe[j];
        }
    }
    if (MODE == 1) __syncthreads();

    // ---- coalesced store (+skip+relu for MODE 1) ----
    {
        const float* bounce = (const float*)(smem + OFF_BOUNCE);
#pragma unroll
        for (int it = 0; it < 16; ++it) {
            int idx4 = tid + it * 256;      // 4096 float4
            int row = idx4 >> 5, c4 = idx4 & 31;
            int grow = row0 + row;
            if (grow < N_NODES) {
                float4 v = *(const float4*)(bounce + row * BSTRIDE + c4 * 4);
                if (MODE == 1) {
                    if (skip) {
                        float4 sk = *(const float4*)(skip + (size_t)grow * HID + c4 * 4);
                        v.x += sk.x; v.y += sk.y; v.z += sk.z; v.w += sk.w;
                    }
                    v.x = fmaxf(v.x, 0.f); v.y = fmaxf(v.y, 0.f);
                    v.z = fmaxf(v.z, 0.f); v.w = fmaxf(v.w, 0.f);
                }
                *(float4*)(out + (size_t)grow * HID + c4 * 4) = v;
            }
        }
    }
}

// ---------------- launch ----------------
extern "C" void kernel_launch(void* const* d_in, const int* in_sizes, int n_in,
                              void* d_out, int out_size)
{
    const float* x       = (const float*)d_in[0];
    const int*   ei      = (const int*)  d_in[1];
    const float* emb_W   = (const float*)d_in[2];
    const float* emb_b   = (const float*)d_in[3];
    const float* lin_l_W = (const float*)d_in[4];
    const float* lin_l_b = (const float*)d_in[5];
    const float* lin_r_W = (const float*)d_in[6];
    const float* ln_g    = (const float*)d_in[7];
    const float* ln_b    = (const float*)d_in[8];
    const float* fus_W1  = (const float*)d_in[9];
    const float* fus_b1  = (const float*)d_in[10];
    const float* fus_W2  = (const float*)d_in[11];
    const float* fus_b2  = (const float*)d_in[12];
    float* out = (float*)d_out;

    float *reps, *agg;
    int* degi;
    cudaGetSymbolAddress((void**)&reps, g_reps);
    cudaGetSymbolAddress((void**)&agg,  g_agg);
    cudaGetSymbolAddress((void**)&degi, g_degi);

    cudaFuncSetAttribute(gemm_mma<0>, cudaFuncAttributeMaxDynamicSharedMemorySize, SMEM_TOTAL);
    cudaFuncSetAttribute(gemm_mma<1>, cudaFuncAttributeMaxDynamicSharedMemorySize, SMEM_TOTAL);
    cudaFuncSetAttribute(gemm_mma<2>, cudaFuncAttributeMaxDynamicSharedMemorySize, SMEM_TOTAL);
    cudaFuncSetAttribute(gemm_mma<3>, cudaFuncAttributeMaxDynamicSharedMemorySize, SMEM_TOTAL);

    // weight prep + CSR build
    prep_w<<<(33 * 4096 + 255) / 256, 256>>>(emb_W, lin_l_W, lin_r_W, fus_W1, fus_W2);
    cudaMemsetAsync(degi, 0, N_NODES * sizeof(int));
    deg_kernel<<<(N_EDGES + 255) / 256, 256>>>(ei);
    inv_kernel<<<(N_NODES + 255) / 256, 256>>>();
    scan_kernel<<<1, 1024>>>();
    fill_kernel<<<(N_EDGES + 255) / 256, 256>>>(ei);

    const int GB = (N_NODES + 127) / 128;  // 391

    gemm_mma<0><<<GB, 256, SMEM_TOTAL>>>(x, nullptr, 0, emb_b,
                                         nullptr, nullptr, nullptr, reps);
    for (int i = 0; i < NLAYERS; i++) {
        float* h  = reps + (size_t)i * N_NODES * HID;
        float* hn = reps + (size_t)(i + 1) * N_NODES * HID;
        agg_kernel<<<(N_NODES * 32 + 255) / 256, 256>>>(h);
        gemm_mma<1><<<GB, 256, SMEM_TOTAL>>>(agg, h, 5 + i * 4,
                                             lin_l_b + i * HID,
                                             ln_g + i * HID, ln_b + i * HID,
                                             (i > 0) ? h : nullptr, hn);
    }
    gemm_mma<2><<<GB, 256, SMEM_TOTAL>>>(reps, nullptr, 21, fus_b1,
                                         nullptr, nullptr, nullptr, agg);
    gemm_mma<3><<<GB, 256, SMEM_TOTAL>>>(agg, nullptr, 31, fus_b2,
                                         nullptr, nullptr, nullptr, out);
}

// round 9
// speedup vs baseline: 2.8797x; 1.1081x over previous
#include <cuda_runtime.h>
#include <cuda_bf16.h>
#include <cstdint>

#define N_NODES 50000
#define N_EDGES 800000
#define IN_DIM 300
#define HID 128
#define NLAYERS 4
#define SCAN_BLOCKS ((N_NODES + 255) / 256)   // 196

// ---------------- device scratch (allocation-free) ----------------
__device__ float g_reps[(NLAYERS + 1) * N_NODES * HID];
__device__ float g_agg[N_NODES * HID];
__device__ float g_inv[N_NODES];
__device__ int   g_degi[N_NODES];
__device__ int   g_rowptr[N_NODES + 1];
__device__ int   g_cursor[N_NODES];
__device__ int   g_col[N_EDGES];
__device__ int   g_bsum[SCAN_BLOCKS];
__device__ int   g_boff[SCAN_BLOCKS];
// pre-transposed weight chunks, bf16 hi/lo: 33 chunks x [128 n x 32 words(64 bf16 k)]
__device__ unsigned int g_whi[33 * 4096];
__device__ unsigned int g_wlo[33 * 4096];

// ---------------- helpers ----------------
__device__ __forceinline__ uint32_t smem_to_u32(const void* p) {
    uint32_t a;
    asm("{ .reg .u64 t; cvta.to.shared.u64 t, %1; cvt.u32.u64 %0, t; }" : "=r"(a) : "l"(p));
    return a;
}
__device__ __forceinline__ void ldsm4(uint32_t* r, uint32_t a) {
    asm volatile("ldmatrix.sync.aligned.m8n8.x4.shared.b16 {%0,%1,%2,%3}, [%4];"
                 : "=r"(r[0]), "=r"(r[1]), "=r"(r[2]), "=r"(r[3]) : "r"(a));
}
__device__ __forceinline__ void ldsm2(uint32_t* r, uint32_t a) {
    asm volatile("ldmatrix.sync.aligned.m8n8.x2.shared.b16 {%0,%1}, [%2];"
                 : "=r"(r[0]), "=r"(r[1]) : "r"(a));
}
__device__ __forceinline__ void mma16816(float* c, const uint32_t* a, const uint32_t* b) {
    asm volatile(
        "mma.sync.aligned.m16n8k16.row.col.f32.bf16.bf16.f32 "
        "{%0,%1,%2,%3},{%4,%5,%6,%7},{%8,%9},{%0,%1,%2,%3};"
        : "+f"(c[0]), "+f"(c[1]), "+f"(c[2]), "+f"(c[3])
        : "r"(a[0]), "r"(a[1]), "r"(a[2]), "r"(a[3]), "r"(b[0]), "r"(b[1]));
}
__device__ __forceinline__ unsigned pack_hi(float a, float b, float& ra, float& rb) {
    __nv_bfloat16 ha = __float2bfloat16(a), hb = __float2bfloat16(b);
    ra = a - __bfloat162float(ha);
    rb = b - __bfloat162float(hb);
    return (unsigned)__bfloat16_as_ushort(ha) | ((unsigned)__bfloat16_as_ushort(hb) << 16);
}
__device__ __forceinline__ unsigned pack_lo(float ra, float rb) {
    return (unsigned)__bfloat16_as_ushort(__float2bfloat16(ra)) |
           ((unsigned)__bfloat16_as_ushort(__float2bfloat16(rb)) << 16);
}

// ---------------- CSR build ----------------
__global__ void deg_kernel(const int* __restrict__ ei) {
    int t = blockIdx.x * blockDim.x + threadIdx.x;
    if (t < N_EDGES) atomicAdd(&g_degi[ei[N_EDGES + t]], 1);
}
__global__ void inv_kernel() {
    int t = blockIdx.x * blockDim.x + threadIdx.x;
    if (t < N_NODES) g_inv[t] = 1.0f / (float)max(g_degi[t], 1);
}

// multi-block scan: (1) per-block exclusive scan + block sums
__global__ __launch_bounds__(256) void scan1_kernel() {
    __shared__ int sm[256];
    int tid = threadIdx.x;
    int i = blockIdx.x * 256 + tid;
    int v = (i < N_NODES) ? g_degi[i] : 0;
    sm[tid] = v;
    __syncthreads();
#pragma unroll
    for (int off = 1; off < 256; off <<= 1) {
        int t = (tid >= off) ? sm[tid - off] : 0;
        __syncthreads();
        sm[tid] += t;
        __syncthreads();
    }
    if (i < N_NODES) g_rowptr[i] = sm[tid] - v;          // block-local exclusive
    if (tid == 255) g_bsum[blockIdx.x] = sm[255];
}
// (2) scan block sums (1 block, 256 threads >= 196)
__global__ __launch_bounds__(256) void scan2_kernel() {
    __shared__ int sm[256];
    int tid = threadIdx.x;
    int v = (tid < SCAN_BLOCKS) ? g_bsum[tid] : 0;
    sm[tid] = v;
    __syncthreads();
#pragma unroll
    for (int off = 1; off < 256; off <<= 1) {
        int t = (tid >= off) ? sm[tid - off] : 0;
        __syncthreads();
        sm[tid] += t;
        __syncthreads();
    }
    if (tid < SCAN_BLOCKS) g_boff[tid] = sm[tid] - v;    // exclusive
}
// (3) add block offsets, init cursor
__global__ __launch_bounds__(256) void scan3_kernel() {
    int tid = threadIdx.x;
    int i = blockIdx.x * 256 + tid;
    if (i < N_NODES) {
        int r = g_rowptr[i] + g_boff[blockIdx.x];
        g_rowptr[i] = r;
        g_cursor[i] = r;
    }
    if (i == 0) g_rowptr[N_NODES] = N_EDGES;
}

__global__ void fill_kernel(const int* __restrict__ ei) {
    int t = blockIdx.x * blockDim.x + threadIdx.x;
    if (t >= N_EDGES) return;
    int dst = ei[N_EDGES + t];
    int pos = atomicAdd(&g_cursor[dst], 1);
    g_col[pos] = ei[t];
}

// ---------------- gather-only mean aggregation (warp per node) ----------------
__global__ __launch_bounds__(256) void agg_kernel(const float* __restrict__ h) {
    int gt = blockIdx.x * blockDim.x + threadIdx.x;
    int node = gt >> 5;
    if (node >= N_NODES) return;
    int lane = gt & 31;
    int beg = g_rowptr[node];
    int end = g_rowptr[node + 1];
    float ax = 0.f, ay = 0.f, az = 0.f, aw = 0.f;
    int e = beg;
    for (; e + 8 <= end; e += 8) {
        float4 v[8];
#pragma unroll
        for (int j = 0; j < 8; j++) {
            int s = __ldg(&g_col[e + j]);
            v[j] = *(const float4*)(h + (size_t)s * HID + lane * 4);
        }
#pragma unroll
        for (int j = 0; j < 8; j++) {
            ax += v[j].x; ay += v[j].y; az += v[j].z; aw += v[j].w;
        }
    }
    for (; e < end; e++) {
        int s = __ldg(&g_col[e]);
        float4 v = *(const float4*)(h + (size_t)s * HID + lane * 4);
        ax += v.x; ay += v.y; az += v.z; aw += v.w;
    }
    float inv = g_inv[node];
    float4 o = make_float4(ax * inv, ay * inv, az * inv, aw * inv);
    *(float4*)(g_agg + (size_t)node * HID + lane * 4) = o;
}

// ---------------- weight prep: transpose + bf16 hi/lo split ----------------
__global__ void prep_w(const float* __restrict__ embW, const float* __restrict__ llW,
                       const float* __restrict__ lrW, const float* __restrict__ f1W,
                       const float* __restrict__ f2W) {
    int t = blockIdx.x * blockDim.x + threadIdx.x;
    if (t >= 33 * 4096) return;
    int chunk = t >> 12, w = t & 4095, n = w >> 5, kp = w & 31, k = kp * 2;
    float v0 = 0.f, v1 = 0.f;
    if (chunk < 5) {
        int kg = chunk * 64 + k;
        if (kg < IN_DIM)     v0 = embW[(size_t)kg * HID + n];
        if (kg + 1 < IN_DIM) v1 = embW[(size_t)(kg + 1) * HID + n];
    } else if (chunk < 21) {
        int L = (chunk - 5) >> 2, c = (chunk - 5) & 3;
        int kg = c * 64 + k;
        const float* W = (kg < 128) ? (llW + (size_t)L * HID * HID + (size_t)kg * HID)
                                    : (lrW + (size_t)L * HID * HID + (size_t)(kg - 128) * HID);
        v0 = W[n]; v1 = W[HID + n];
    } else if (chunk < 31) {
        int kg = (chunk - 21) * 64 + k;
        v0 = f1W[(size_t)kg * HID + n]; v1 = f1W[(size_t)(kg + 1) * HID + n];
    } else {
        int kg = (chunk - 31) * 64 + k;
        v0 = f2W[(size_t)kg * HID + n]; v1 = f2W[(size_t)(kg + 1) * HID + n];
    }
    float r0, r1;
    unsigned hp = pack_hi(v0, v1, r0, r1);
    unsigned lp = pack_lo(r0, r1);
    g_whi[chunk * 4096 + n * 32 + kp] = hp;
    g_wlo[chunk * 4096 + n * 32 + kp] = lp;
}

// ---------------- mma.sync GEMM family ----------------
#define OFF_BIAS 0
#define OFF_G    512
#define OFF_B    1024
#define OFF_AH   2048
#define OFF_AL   (OFF_AH + 128 * 144)
#define OFF_BH   (OFF_AL + 128 * 144)
#define OFF_BL   (OFF_BH + 128 * 144)
#define SMEM_TOTAL (OFF_BL + 128 * 144)
#define OFF_BOUNCE OFF_AH
#define BSTRIDE 132

template <int MODE>
__global__ __launch_bounds__(256)
void gemm_mma(const float* __restrict__ A, const float* __restrict__ A2, int wc0,
              const float* __restrict__ bias, const float* __restrict__ lng,
              const float* __restrict__ lnb, const float* __restrict__ skip,
              float* __restrict__ out)
{
    extern __shared__ char smem[];
    uint32_t sb = smem_to_u32(smem);
    int tid = threadIdx.x, wid = tid >> 5, lane = tid & 31;
    int warp_m = wid & 3, warp_n = wid >> 2;
    int row0 = blockIdx.x * 128;
    const int nch = (MODE == 0) ? 5 : (MODE == 1) ? 4 : (MODE == 2) ? 10 : 2;

    if (tid < HID) {
        *(float*)(smem + OFF_BIAS + tid * 4) = bias[tid];
        if (MODE == 1) {
            *(float*)(smem + OFF_G + tid * 4) = lng[tid];
            *(float*)(smem + OFF_B + tid * 4) = lnb[tid];
        }
    }

    float acc[2][8][4];
#pragma unroll
    for (int mt = 0; mt < 2; mt++)
#pragma unroll
        for (int nt = 0; nt < 8; nt++)
#pragma unroll
            for (int q = 0; q < 4; q++) acc[mt][nt][q] = 0.f;

    uint32_t aOff = sb + (uint32_t)((warp_m * 32 + (lane & 15)) * 144 + (lane >> 4) * 16);
    uint32_t bOff = sb + (uint32_t)((warp_n * 64 + (lane & 7)) * 144 + ((lane >> 3) & 1) * 16);

    for (int c = 0; c < nch; ++c) {
        __syncthreads();
        // ---- fill A_hi / A_lo (128 rows x 64 k bf16, 144B stride) ----
#pragma unroll
        for (int it = 0; it < 8; ++it) {
            int idx = tid + it * 256;
            int row = idx >> 4, q = idx & 15, k = q * 4;
            int kg = c * 64 + k, grow = row0 + row;
            float4 v = make_float4(0.f, 0.f, 0.f, 0.f);
            if (grow < N_NODES) {
                if (MODE == 0) {
                    if (kg < IN_DIM) v = *(const float4*)(A + (size_t)grow * IN_DIM + kg);
                } else if (MODE == 1) {
                    v = (kg < 128) ? *(const float4*)(A  + (size_t)grow * HID + kg)
                                   : *(const float4*)(A2 + (size_t)grow * HID + kg - 128);
                } else if (MODE == 2) {
                    int rep = kg >> 7;
                    v = *(const float4*)(A + (size_t)rep * ((size_t)N_NODES * HID) +
                                         (size_t)grow * HID + (kg & 127));
                } else {
                    v = *(const float4*)(A + (size_t)grow * HID + kg);
                }
            }
            float r0, r1, r2, r3;
            unsigned h01 = pack_hi(v.x, v.y, r0, r1);
            unsigned h23 = pack_hi(v.z, v.w, r2, r3);
            unsigned l01 = pack_lo(r0, r1);
            unsigned l23 = pack_lo(r2, r3);
            int off = row * 144 + k * 2;
            *(uint2*)(smem + OFF_AH + off) = make_uint2(h01, h23);
            *(uint2*)(smem + OFF_AL + off) = make_uint2(l01, l23);
        }
        // ---- copy B chunk ----
        {
            const uint4* srcH = (const uint4*)(g_whi + (size_t)(wc0 + c) * 4096);
            const uint4* srcL = (const uint4*)(g_wlo + (size_t)(wc0 + c) * 4096);
#pragma unroll
            for (int it = 0; it < 4; ++it) {
                int idx = tid + it * 256;
                int row = idx >> 3, j = idx & 7;
                int off = row * 144 + j * 16;
                *(uint4*)(smem + OFF_BH + off) = srcH[idx];
                *(uint4*)(smem + OFF_BL + off) = srcL[idx];
            }
        }
        __syncthreads();
        // ---- compute: 4 k16 steps ----
#pragma unroll
        for (int ks = 0; ks < 4; ++ks) {
            uint32_t ah[2][4], al[2][4];
#pragma unroll
            for (int mt = 0; mt < 2; mt++) {
                ldsm4(ah[mt], aOff + OFF_AH + mt * 16 * 144 + ks * 32);
                ldsm4(al[mt], aOff + OFF_AL + mt * 16 * 144 + ks * 32);
            }
#pragma unroll
            for (int nt = 0; nt < 8; ++nt) {
                uint32_t bh[2], bl[2];
                ldsm2(bh, bOff + OFF_BH + nt * 8 * 144 + ks * 32);
                ldsm2(bl, bOff + OFF_BL + nt * 8 * 144 + ks * 32);
#pragma unroll
                for (int mt = 0; mt < 2; mt++) {
                    mma16816(acc[mt][nt], ah[mt], bh);
                    mma16816(acc[mt][nt], ah[mt], bl);
                    mma16816(acc[mt][nt], al[mt], bh);
                }
            }
        }
    }
    __syncthreads();

    // ---- dump accs (+bias, +relu for MODE 0/2) to bounce ----
    {
        float* bounce = (float*)(smem + OFF_BOUNCE);
        const float* sbias = (const float*)(smem + OFF_BIAS);
        int tq = lane >> 2, tr = lane & 3;
#pragma unroll
        for (int mt = 0; mt < 2; mt++) {
#pragma unroll
            for (int nt = 0; nt < 8; nt++) {
                int col = warp_n * 64 + nt * 8 + tr * 2;
                float b0 = sbias[col], b1 = sbias[col + 1];
                int r0 = warp_m * 32 + mt * 16 + tq;
                float x0 = acc[mt][nt][0] + b0, x1 = acc[mt][nt][1] + b1;
                float x2 = acc[mt][nt][2] + b0, x3 = acc[mt][nt][3] + b1;
                if (MODE == 0 || MODE == 2) {
                    x0 = fmaxf(x0, 0.f); x1 = fmaxf(x1, 0.f);
                    x2 = fmaxf(x2, 0.f); x3 = fmaxf(x3, 0.f);
                }
                *(float2*)(bounce + r0 * BSTRIDE + col)       = make_float2(x0, x1);
                *(float2*)(bounce + (r0 + 8) * BSTRIDE + col) = make_float2(x2, x3);
            }
        }
    }
    __syncthreads();

    // ---- LN pass (MODE 1): thread per row ----
    if (MODE == 1 && tid < 128) {
        float* bounce = (float*)(smem + OFF_BOUNCE);
        const float* sg = (const float*)(smem + OFF_G);
        const float* sbe = (const float*)(smem + OFF_B);
        float s = 0.f, s2 = 0.f;
#pragma unroll
        for (int j = 0; j < HID; j++) {
            float x = bounce[tid * BSTRIDE + j];
            s += x; s2 += x * x;
        }
        float mean = s * (1.0f / HID);
        float var = s2 * (1.0f / HID) - mean * mean;
        float rs = rsqrtf(var + 1e-5f);
#pragma unroll
        for (int j = 0; j < HID; j++) {
            float x = bounce[tid * BSTRIDE + j];
            bounce[tid * BSTRIDE + j] = (x - mean) * rs * sg[j] + sbe[j];
        }
    }
    if (MODE == 1) __syncthreads();

    // ---- coalesced store (+skip+relu for MODE 1) ----
    {
        const float* bounce = (const float*)(smem + OFF_BOUNCE);
#pragma unroll
        for (int it = 0; it < 16; ++it) {
            int idx4 = tid + it * 256;
            int row = idx4 >> 5, c4 = idx4 & 31;
            int grow = row0 + row;
            if (grow < N_NODES) {
                float4 v = *(const float4*)(bounce + row * BSTRIDE + c4 * 4);
                if (MODE == 1) {
                    if (skip) {
                        float4 sk = *(const float4*)(skip + (size_t)grow * HID + c4 * 4);
                        v.x += sk.x; v.y += sk.y; v.z += sk.z; v.w += sk.w;
                    }
                    v.x = fmaxf(v.x, 0.f); v.y = fmaxf(v.y, 0.f);
                    v.z = fmaxf(v.z, 0.f); v.w = fmaxf(v.w, 0.f);
                }
                *(float4*)(out + (size_t)grow * HID + c4 * 4) = v;
            }
        }
    }
}

// ---------------- launch ----------------
extern "C" void kernel_launch(void* const* d_in, const int* in_sizes, int n_in,
                              void* d_out, int out_size)
{
    const float* x       = (const float*)d_in[0];
    const int*   ei      = (const int*)  d_in[1];
    const float* emb_W   = (const float*)d_in[2];
    const float* emb_b   = (const float*)d_in[3];
    const float* lin_l_W = (const float*)d_in[4];
    const float* lin_l_b = (const float*)d_in[5];
    const float* lin_r_W = (const float*)d_in[6];
    const float* ln_g    = (const float*)d_in[7];
    const float* ln_b    = (const float*)d_in[8];
    const float* fus_W1  = (const float*)d_in[9];
    const float* fus_b1  = (const float*)d_in[10];
    const float* fus_W2  = (const float*)d_in[11];
    const float* fus_b2  = (const float*)d_in[12];
    float* out = (float*)d_out;

    float *reps, *agg;
    int* degi;
    cudaGetSymbolAddress((void**)&reps, g_reps);
    cudaGetSymbolAddress((void**)&agg,  g_agg);
    cudaGetSymbolAddress((void**)&degi, g_degi);

    cudaFuncSetAttribute(gemm_mma<0>, cudaFuncAttributeMaxDynamicSharedMemorySize, SMEM_TOTAL);
    cudaFuncSetAttribute(gemm_mma<1>, cudaFuncAttributeMaxDynamicSharedMemorySize, SMEM_TOTAL);
    cudaFuncSetAttribute(gemm_mma<2>, cudaFuncAttributeMaxDynamicSharedMemorySize, SMEM_TOTAL);
    cudaFuncSetAttribute(gemm_mma<3>, cudaFuncAttributeMaxDynamicSharedMemorySize, SMEM_TOTAL);

    // weight prep + CSR build
    prep_w<<<(33 * 4096 + 255) / 256, 256>>>(emb_W, lin_l_W, lin_r_W, fus_W1, fus_W2);
    cudaMemsetAsync(degi, 0, N_NODES * sizeof(int));
    deg_kernel<<<(N_EDGES + 255) / 256, 256>>>(ei);
    inv_kernel<<<(N_NODES + 255) / 256, 256>>>();
    scan1_kernel<<<SCAN_BLOCKS, 256>>>();
    scan2_kernel<<<1, 256>>>();
    scan3_kernel<<<SCAN_BLOCKS, 256>>>();
    fill_kernel<<<(N_EDGES + 255) / 256, 256>>>(ei);

    const int GB = (N_NODES + 127) / 128;  // 391

    gemm_mma<0><<<GB, 256, SMEM_TOTAL>>>(x, nullptr, 0, emb_b,
                                         nullptr, nullptr, nullptr, reps);
    for (int i = 0; i < NLAYERS; i++) {
        float* h  = reps + (size_t)i * N_NODES * HID;
        float* hn = reps + (size_t)(i + 1) * N_NODES * HID;
        agg_kernel<<<(N_NODES * 32 + 255) / 256, 256>>>(h);
        gemm_mma<1><<<GB, 256, SMEM_TOTAL>>>(agg, h, 5 + i * 4,
                                             lin_l_b + i * HID,
                                             ln_g + i * HID, ln_b + i * HID,
                                             (i > 0) ? h : nullptr, hn);
    }
    gemm_mma<2><<<GB, 256, SMEM_TOTAL>>>(reps, nullptr, 21, fus_b1,
                                         nullptr, nullptr, nullptr, agg);
    gemm_mma<3><<<GB, 256, SMEM_TOTAL>>>(agg, nullptr, 31, fus_b2,
                                         nullptr, nullptr, nullptr, out);
}

// round 10
// speedup vs baseline: 3.3001x; 1.1460x over previous
#include <cuda_runtime.h>
#include <cuda_bf16.h>
#include <cstdint>

#define N_NODES 50000
#define N_EDGES 800000
#define IN_DIM 300
#define HID 128
#define NLAYERS 4
#define SCAN_BLOCKS ((N_NODES + 255) / 256)   // 196

// ---------------- device scratch (allocation-free) ----------------
__device__ float g_reps[(NLAYERS + 1) * N_NODES * HID];
__device__ float g_agg[N_NODES * HID];
__device__ float g_inv[N_NODES];
__device__ int   g_degi[N_NODES];
__device__ int   g_rowptr[N_NODES + 1];
__device__ int   g_cursor[N_NODES];
__device__ int   g_col[N_EDGES];
__device__ int   g_bsum[SCAN_BLOCKS];
__device__ int   g_boff[SCAN_BLOCKS];
// pre-transposed weight chunks, bf16 hi/lo: 33 chunks x [128 n x 32 words(64 bf16 k)]
__device__ unsigned int g_whi[33 * 4096];
__device__ unsigned int g_wlo[33 * 4096];

// ---------------- helpers ----------------
__device__ __forceinline__ uint32_t smem_to_u32(const void* p) {
    uint32_t a;
    asm("{ .reg .u64 t; cvta.to.shared.u64 t, %1; cvt.u32.u64 %0, t; }" : "=r"(a) : "l"(p));
    return a;
}
__device__ __forceinline__ void ldsm4(uint32_t* r, uint32_t a) {
    asm volatile("ldmatrix.sync.aligned.m8n8.x4.shared.b16 {%0,%1,%2,%3}, [%4];"
                 : "=r"(r[0]), "=r"(r[1]), "=r"(r[2]), "=r"(r[3]) : "r"(a));
}
__device__ __forceinline__ void mma16816(float* c, const uint32_t* a, const uint32_t* b) {
    asm volatile(
        "mma.sync.aligned.m16n8k16.row.col.f32.bf16.bf16.f32 "
        "{%0,%1,%2,%3},{%4,%5,%6,%7},{%8,%9},{%0,%1,%2,%3};"
        : "+f"(c[0]), "+f"(c[1]), "+f"(c[2]), "+f"(c[3])
        : "r"(a[0]), "r"(a[1]), "r"(a[2]), "r"(a[3]), "r"(b[0]), "r"(b[1]));
}
__device__ __forceinline__ void cp_async16(uint32_t dst, const void* src) {
    uint64_t ga;
    asm("cvta.to.global.u64 %0, %1;" : "=l"(ga) : "l"(src));
    asm volatile("cp.async.cg.shared.global [%0], [%1], 16;" :: "r"(dst), "l"(ga) : "memory");
}
__device__ __forceinline__ void cp_commit() { asm volatile("cp.async.commit_group;" ::: "memory"); }
template <int N>
__device__ __forceinline__ void cp_wait() { asm volatile("cp.async.wait_group %0;" :: "n"(N) : "memory"); }

__device__ __forceinline__ unsigned pack_hi(float a, float b, float& ra, float& rb) {
    __nv_bfloat16 ha = __float2bfloat16(a), hb = __float2bfloat16(b);
    ra = a - __bfloat162float(ha);
    rb = b - __bfloat162float(hb);
    return (unsigned)__bfloat16_as_ushort(ha) | ((unsigned)__bfloat16_as_ushort(hb) << 16);
}
__device__ __forceinline__ unsigned pack_lo(float ra, float rb) {
    return (unsigned)__bfloat16_as_ushort(__float2bfloat16(ra)) |
           ((unsigned)__bfloat16_as_ushort(__float2bfloat16(rb)) << 16);
}

// ---------------- CSR build ----------------
__global__ void deg_kernel(const int* __restrict__ ei) {
    int t = blockIdx.x * blockDim.x + threadIdx.x;
    if (t < N_EDGES) atomicAdd(&g_degi[ei[N_EDGES + t]], 1);
}
__global__ void inv_kernel() {
    int t = blockIdx.x * blockDim.x + threadIdx.x;
    if (t < N_NODES) g_inv[t] = 1.0f / (float)max(g_degi[t], 1);
}
__global__ __launch_bounds__(256) void scan1_kernel() {
    __shared__ int sm[256];
    int tid = threadIdx.x;
    int i = blockIdx.x * 256 + tid;
    int v = (i < N_NODES) ? g_degi[i] : 0;
    sm[tid] = v;
    __syncthreads();
#pragma unroll
    for (int off = 1; off < 256; off <<= 1) {
        int t = (tid >= off) ? sm[tid - off] : 0;
        __syncthreads();
        sm[tid] += t;
        __syncthreads();
    }
    if (i < N_NODES) g_rowptr[i] = sm[tid] - v;
    if (tid == 255) g_bsum[blockIdx.x] = sm[255];
}
__global__ __launch_bounds__(256) void scan2_kernel() {
    __shared__ int sm[256];
    int tid = threadIdx.x;
    int v = (tid < SCAN_BLOCKS) ? g_bsum[tid] : 0;
    sm[tid] = v;
    __syncthreads();
#pragma unroll
    for (int off = 1; off < 256; off <<= 1) {
        int t = (tid >= off) ? sm[tid - off] : 0;
        __syncthreads();
        sm[tid] += t;
        __syncthreads();
    }
    if (tid < SCAN_BLOCKS) g_boff[tid] = sm[tid] - v;
}
__global__ __launch_bounds__(256) void scan3_kernel() {
    int tid = threadIdx.x;
    int i = blockIdx.x * 256 + tid;
    if (i < N_NODES) {
        int r = g_rowptr[i] + g_boff[blockIdx.x];
        g_rowptr[i] = r;
        g_cursor[i] = r;
    }
    if (i == 0) g_rowptr[N_NODES] = N_EDGES;
}
__global__ void fill_kernel(const int* __restrict__ ei) {
    int t = blockIdx.x * blockDim.x + threadIdx.x;
    if (t >= N_EDGES) return;
    int dst = ei[N_EDGES + t];
    int pos = atomicAdd(&g_cursor[dst], 1);
    g_col[pos] = ei[t];
}

// ---------------- gather-only mean aggregation (warp per node) ----------------
__global__ __launch_bounds__(256) void agg_kernel(const float* __restrict__ h) {
    int gt = blockIdx.x * blockDim.x + threadIdx.x;
    int node = gt >> 5;
    if (node >= N_NODES) return;
    int lane = gt & 31;
    int beg = g_rowptr[node];
    int end = g_rowptr[node + 1];
    float ax = 0.f, ay = 0.f, az = 0.f, aw = 0.f;
    int e = beg;
    for (; e + 8 <= end; e += 8) {
        float4 v[8];
#pragma unroll
        for (int j = 0; j < 8; j++) {
            int s = __ldg(&g_col[e + j]);
            v[j] = *(const float4*)(h + (size_t)s * HID + lane * 4);
        }
#pragma unroll
        for (int j = 0; j < 8; j++) {
            ax += v[j].x; ay += v[j].y; az += v[j].z; aw += v[j].w;
        }
    }
    for (; e < end; e++) {
        int s = __ldg(&g_col[e]);
        float4 v = *(const float4*)(h + (size_t)s * HID + lane * 4);
        ax += v.x; ay += v.y; az += v.z; aw += v.w;
    }
    float inv = g_inv[node];
    float4 o = make_float4(ax * inv, ay * inv, az * inv, aw * inv);
    *(float4*)(g_agg + (size_t)node * HID + lane * 4) = o;
}

// ---------------- weight prep: transpose + bf16 hi/lo split ----------------
__global__ void prep_w(const float* __restrict__ embW, const float* __restrict__ llW,
                       const float* __restrict__ lrW, const float* __restrict__ f1W,
                       const float* __restrict__ f2W) {
    int t = blockIdx.x * blockDim.x + threadIdx.x;
    if (t >= 33 * 4096) return;
    int chunk = t >> 12, w = t & 4095, n = w >> 5, kp = w & 31, k = kp * 2;
    float v0 = 0.f, v1 = 0.f;
    if (chunk < 5) {
        int kg = chunk * 64 + k;
        if (kg < IN_DIM)     v0 = embW[(size_t)kg * HID + n];
        if (kg + 1 < IN_DIM) v1 = embW[(size_t)(kg + 1) * HID + n];
    } else if (chunk < 21) {
        int L = (chunk - 5) >> 2, c = (chunk - 5) & 3;
        int kg = c * 64 + k;
        const float* W = (kg < 128) ? (llW + (size_t)L * HID * HID + (size_t)kg * HID)
                                    : (lrW + (size_t)L * HID * HID + (size_t)(kg - 128) * HID);
        v0 = W[n]; v1 = W[HID + n];
    } else if (chunk < 31) {
        int kg = (chunk - 21) * 64 + k;
        v0 = f1W[(size_t)kg * HID + n]; v1 = f1W[(size_t)(kg + 1) * HID + n];
    } else {
        int kg = (chunk - 31) * 64 + k;
        v0 = f2W[(size_t)kg * HID + n]; v1 = f2W[(size_t)(kg + 1) * HID + n];
    }
    float r0, r1;
    unsigned hp = pack_hi(v0, v1, r0, r1);
    unsigned lp = pack_lo(r0, r1);
    g_whi[chunk * 4096 + n * 32 + kp] = hp;
    g_wlo[chunk * 4096 + n * 32 + kp] = lp;
}

// ---------------- mma.sync GEMM family (cp.async B double-buffer) ----------------
#define OFF_BIAS 0
#define OFF_G    512
#define OFF_B    1024
#define OFF_AH   2048
#define OFF_AL   (OFF_AH + 18432)      // 20480
#define OFF_BB0  38912
#define OFF_BB1  75776
#define BL_OFF   18432                 // BL within a B buffer
#define SMEM_TOTAL 112640
#define OFF_BOUNCE OFF_AH
#define BSTRIDE 132

__device__ __forceinline__ void issueB(uint32_t sb, uint32_t bufoff, int chunk, int tid) {
#pragma unroll
    for (int it = 0; it < 8; ++it) {
        int idx = tid + it * 256;          // 0..2047
        int half = idx >> 10, w = idx & 1023;
        int row = w >> 3, j = w & 7;
        uint32_t dst = sb + bufoff + half * BL_OFF + row * 144 + j * 16;
        const unsigned* src = (half ? g_wlo : g_whi) + (size_t)chunk * 4096 + w * 4;
        cp_async16(dst, src);
    }
}

// MODE 0: relu(x @ embW + b)                       K=300 (5 chunks)
// MODE 1: relu(LN(agg@Wl + b + h@Wr) [+skip])      K=256 (4 chunks)
// MODE 2: relu(concat @ fusW1 + b)                 K=640 (10 chunks)
// MODE 3: A @ fusW2 + b                            K=128 (2 chunks)
template <int MODE>
__global__ __launch_bounds__(256)
void gemm_mma(const float* __restrict__ A, const float* __restrict__ A2, int wc0,
              const float* __restrict__ bias, const float* __restrict__ lng,
              const float* __restrict__ lnb, const float* __restrict__ skip,
              float* __restrict__ out)
{
    extern __shared__ char smem[];
    uint32_t sb = smem_to_u32(smem);
    int tid = threadIdx.x, wid = tid >> 5, lane = tid & 31;
    int warp_m = wid & 3, warp_n = wid >> 2;
    int row0 = blockIdx.x * 128;
    const int nch = (MODE == 0) ? 5 : (MODE == 1) ? 4 : (MODE == 2) ? 10 : 2;

    if (tid < HID) {
        *(float*)(smem + OFF_BIAS + tid * 4) = bias[tid];
        if (MODE == 1) {
            *(float*)(smem + OFF_G + tid * 4) = lng[tid];
            *(float*)(smem + OFF_B + tid * 4) = lnb[tid];
        }
    }

    float acc[2][8][4];
#pragma unroll
    for (int mt = 0; mt < 2; mt++)
#pragma unroll
        for (int nt = 0; nt < 8; nt++)
#pragma unroll
            for (int q = 0; q < 4; q++) acc[mt][nt][q] = 0.f;

    uint32_t aOff = sb + (uint32_t)((warp_m * 32 + (lane & 15)) * 144 + (lane >> 4) * 16);
    // x4 B fragment address: 16 n-rows per load
    uint32_t bOff4 = sb + (uint32_t)((warp_n * 64 + ((lane >> 4) & 1) * 8 + (lane & 7)) * 144 +
                                     ((lane >> 3) & 1) * 16);

    // prologue: prefetch B chunk 0
    issueB(sb, OFF_BB0, wc0, tid);
    cp_commit();

    for (int c = 0; c < nch; ++c) {
        __syncthreads();   // previous compute done: A smem & next B buffer free
        // ---- fill A_hi / A_lo (128 rows x 64 k bf16, 144B stride) ----
#pragma unroll
        for (int it = 0; it < 8; ++it) {
            int idx = tid + it * 256;
            int row = idx >> 4, q = idx & 15, k = q * 4;
            int kg = c * 64 + k, grow = row0 + row;
            float4 v = make_float4(0.f, 0.f, 0.f, 0.f);
            if (grow < N_NODES) {
                if (MODE == 0) {
                    if (kg < IN_DIM) v = *(const float4*)(A + (size_t)grow * IN_DIM + kg);
                } else if (MODE == 1) {
                    v = (kg < 128) ? *(const float4*)(A  + (size_t)grow * HID + kg)
                                   : *(const float4*)(A2 + (size_t)grow * HID + kg - 128);
                } else if (MODE == 2) {
                    int rep = kg >> 7;
                    v = *(const float4*)(A + (size_t)rep * ((size_t)N_NODES * HID) +
                                         (size_t)grow * HID + (kg & 127));
                } else {
                    v = *(const float4*)(A + (size_t)grow * HID + kg);
                }
            }
            float r0, r1, r2, r3;
            unsigned h01 = pack_hi(v.x, v.y, r0, r1);
            unsigned h23 = pack_hi(v.z, v.w, r2, r3);
            unsigned l01 = pack_lo(r0, r1);
            unsigned l23 = pack_lo(r2, r3);
            int off = row * 144 + k * 2;
            *(uint2*)(smem + OFF_AH + off) = make_uint2(h01, h23);
            *(uint2*)(smem + OFF_AL + off) = make_uint2(l01, l23);
        }
        // ---- prefetch next B chunk; wait for current ----
        if (c + 1 < nch) {
            issueB(sb, ((c + 1) & 1) ? OFF_BB1 : OFF_BB0, wc0 + c + 1, tid);
            cp_commit();
            cp_wait<1>();
        } else {
            cp_wait<0>();
        }
        __syncthreads();
        // ---- compute: 4 k16 steps ----
        uint32_t bbase = (c & 1) ? OFF_BB1 : OFF_BB0;
#pragma unroll
        for (int ks = 0; ks < 4; ++ks) {
            uint32_t ah[2][4], al[2][4];
#pragma unroll
            for (int mt = 0; mt < 2; mt++) {
                ldsm4(ah[mt], aOff + OFF_AH + mt * 16 * 144 + ks * 32);
                ldsm4(al[mt], aOff + OFF_AL + mt * 16 * 144 + ks * 32);
            }
#pragma unroll
            for (int nt2 = 0; nt2 < 4; ++nt2) {
                uint32_t bh[4], bl[4];
                ldsm4(bh, bOff4 + bbase + nt2 * 16 * 144 + ks * 32);
                ldsm4(bl, bOff4 + bbase + BL_OFF + nt2 * 16 * 144 + ks * 32);
#pragma unroll
                for (int mt = 0; mt < 2; mt++) {
                    mma16816(acc[mt][2 * nt2],     ah[mt], &bh[0]);
                    mma16816(acc[mt][2 * nt2 + 1], ah[mt], &bh[2]);
                    mma16816(acc[mt][2 * nt2],     ah[mt], &bl[0]);
                    mma16816(acc[mt][2 * nt2 + 1], ah[mt], &bl[2]);
                    mma16816(acc[mt][2 * nt2],     al[mt], &bh[0]);
                    mma16816(acc[mt][2 * nt2 + 1], al[mt], &bh[2]);
                }
            }
        }
    }
    __syncthreads();

    // ---- dump accs (+bias, +relu for MODE 0/2) to bounce ----
    {
        float* bounce = (float*)(smem + OFF_BOUNCE);
        const float* sbias = (const float*)(smem + OFF_BIAS);
        int tq = lane >> 2, tr = lane & 3;
#pragma unroll
        for (int mt = 0; mt < 2; mt++) {
#pragma unroll
            for (int nt = 0; nt < 8; nt++) {
                int col = warp_n * 64 + nt * 8 + tr * 2;
                float b0 = sbias[col], b1 = sbias[col + 1];
                int r0 = warp_m * 32 + mt * 16 + tq;
                float x0 = acc[mt][nt][0] + b0, x1 = acc[mt][nt][1] + b1;
                float x2 = acc[mt][nt][2] + b0, x3 = acc[mt][nt][3] + b1;
                if (MODE == 0 || MODE == 2) {
                    x0 = fmaxf(x0, 0.f); x1 = fmaxf(x1, 0.f);
                    x2 = fmaxf(x2, 0.f); x3 = fmaxf(x3, 0.f);
                }
                *(float2*)(bounce + r0 * BSTRIDE + col)       = make_float2(x0, x1);
                *(float2*)(bounce + (r0 + 8) * BSTRIDE + col) = make_float2(x2, x3);
            }
        }
    }
    __syncthreads();

    // ---- LN pass (MODE 1): thread per row ----
    if (MODE == 1 && tid < 128) {
        float* bounce = (float*)(smem + OFF_BOUNCE);
        const float* sg = (const float*)(smem + OFF_G);
        const float* sbe = (const float*)(smem + OFF_B);
        float s = 0.f, s2 = 0.f;
#pragma unroll
        for (int j = 0; j < HID; j++) {
            float x = bounce[tid * BSTRIDE + j];
            s += x; s2 += x * x;
        }
        float mean = s * (1.0f / HID);
        float var = s2 * (1.0f / HID) - mean * mean;
        float rs = rsqrtf(var + 1e-5f);
#pragma unroll
        for (int j = 0; j < HID; j++) {
            float x = bounce[tid * BSTRIDE + j];
            bounce[tid * BSTRIDE + j] = (x - mean) * rs * sg[j] + sbe[j];
        }
    }
    if (MODE == 1) __syncthreads();

    // ---- coalesced store (+skip+relu for MODE 1) ----
    {
        const float* bounce = (const float*)(smem + OFF_BOUNCE);
#pragma unroll
        for (int it = 0; it < 16; ++it) {
            int idx4 = tid + it * 256;
            int row = idx4 >> 5, c4 = idx4 & 31;
            int grow = row0 + row;
            if (grow < N_NODES) {
                float4 v = *(const float4*)(bounce + row * BSTRIDE + c4 * 4);
                if (MODE == 1) {
                    if (skip) {
                        float4 sk = *(const float4*)(skip + (size_t)grow * HID + c4 * 4);
                        v.x += sk.x; v.y += sk.y; v.z += sk.z; v.w += sk.w;
                    }
                    v.x = fmaxf(v.x, 0.f); v.y = fmaxf(v.y, 0.f);
                    v.z = fmaxf(v.z, 0.f); v.w = fmaxf(v.w, 0.f);
                }
                *(float4*)(out + (size_t)grow * HID + c4 * 4) = v;
            }
        }
    }
}

// ---------------- launch ----------------
extern "C" void kernel_launch(void* const* d_in, const int* in_sizes, int n_in,
                              void* d_out, int out_size)
{
    const float* x       = (const float*)d_in[0];
    const int*   ei      = (const int*)  d_in[1];
    const float* emb_W   = (const float*)d_in[2];
    const float* emb_b   = (const float*)d_in[3];
    const float* lin_l_W = (const float*)d_in[4];
    const float* lin_l_b = (const float*)d_in[5];
    const float* lin_r_W = (const float*)d_in[6];
    const float* ln_g    = (const float*)d_in[7];
    const float* ln_b    = (const float*)d_in[8];
    const float* fus_W1  = (const float*)d_in[9];
    const float* fus_b1  = (const float*)d_in[10];
    const float* fus_W2  = (const float*)d_in[11];
    const float* fus_b2  = (const float*)d_in[12];
    float* out = (float*)d_out;

    float *reps, *agg;
    int* degi;
    cudaGetSymbolAddress((void**)&reps, g_reps);
    cudaGetSymbolAddress((void**)&agg,  g_agg);
    cudaGetSymbolAddress((void**)&degi, g_degi);

    cudaFuncSetAttribute(gemm_mma<0>, cudaFuncAttributeMaxDynamicSharedMemorySize, SMEM_TOTAL);
    cudaFuncSetAttribute(gemm_mma<1>, cudaFuncAttributeMaxDynamicSharedMemorySize, SMEM_TOTAL);
    cudaFuncSetAttribute(gemm_mma<2>, cudaFuncAttributeMaxDynamicSharedMemorySize, SMEM_TOTAL);
    cudaFuncSetAttribute(gemm_mma<3>, cudaFuncAttributeMaxDynamicSharedMemorySize, SMEM_TOTAL);

    // side stream + fork/join events (host-side objects only; created once)
    static cudaStream_t s2 = nullptr;
    static cudaEvent_t evF = nullptr, evJ = nullptr;
    if (s2 == nullptr) {
        cudaStreamCreateWithFlags(&s2, cudaStreamNonBlocking);
        cudaEventCreateWithFlags(&evF, cudaEventDisableTiming);
        cudaEventCreateWithFlags(&evJ, cudaEventDisableTiming);
    }

    // fork: CSR build on s2, weight prep + embed GEMM on main stream
    cudaEventRecord(evF, 0);
    cudaStreamWaitEvent(s2, evF, 0);
    cudaMemsetAsync(degi, 0, N_NODES * sizeof(int), s2);
    deg_kernel<<<(N_EDGES + 255) / 256, 256, 0, s2>>>(ei);
    inv_kernel<<<(N_NODES + 255) / 256, 256, 0, s2>>>();
    scan1_kernel<<<SCAN_BLOCKS, 256, 0, s2>>>();
    scan2_kernel<<<1, 256, 0, s2>>>();
    scan3_kernel<<<SCAN_BLOCKS, 256, 0, s2>>>();
    fill_kernel<<<(N_EDGES + 255) / 256, 256, 0, s2>>>(ei);
    cudaEventRecord(evJ, s2);

    prep_w<<<(33 * 4096 + 255) / 256, 256>>>(emb_W, lin_l_W, lin_r_W, fus_W1, fus_W2);

    const int GB = (N_NODES + 127) / 128;  // 391

    gemm_mma<0><<<GB, 256, SMEM_TOTAL>>>(x, nullptr, 0, emb_b,
                                         nullptr, nullptr, nullptr, reps);

    // join before aggregation needs CSR
    cudaStreamWaitEvent(0, evJ, 0);

    for (int i = 0; i < NLAYERS; i++) {
        float* h  = reps + (size_t)i * N_NODES * HID;
        float* hn = reps + (size_t)(i + 1) * N_NODES * HID;
        agg_kernel<<<(N_NODES * 32 + 255) / 256, 256>>>(h);
        gemm_mma<1><<<GB, 256, SMEM_TOTAL>>>(agg, h, 5 + i * 4,
                                             lin_l_b + i * HID,
                                             ln_g + i * HID, ln_b + i * HID,
                                             (i > 0) ? h : nullptr, hn);
    }
    gemm_mma<2><<<GB, 256, SMEM_TOTAL>>>(reps, nullptr, 21, fus_b1,
                                         nullptr, nullptr, nullptr, agg);
    gemm_mma<3><<<GB, 256, SMEM_TOTAL>>>(agg, nullptr, 31, fus_b2,
                                         nullptr, nullptr, nullptr, out);
}